// round 14
// baseline (speedup 1.0000x reference)
#include <cuda_runtime.h>

#define DIM   100
#define NW    39
#define NH    4
#define NBLK  4800          // one slice per block
#define NTHR  128
#define NWARP 4
#define NQ    25            // float4 chunks per 100-float row
#define NIT   5             // dual-row iterations per warp (covers 10 rows)

__device__ __forceinline__ float sgn035(float t) {
    return __uint_as_float((__float_as_uint(t) & 0x80000000u) | 0x3EB33333u);
}

// 4 head-score partials over this lane's 4 d-slots (3 FFMA / element)
#define SCORE4(A, W)                                                      \
    {                                                                     \
        _Pragma("unroll")                                                 \
        for (int h = 0; h < NH; h++) {                                    \
            float y, sa, sb;                                              \
            y  = fmaf((W).x, r1[h].x, b1[h].x);                           \
            sa = y * 0.65f;                                               \
            sb = k35.x * fabsf(y);                                        \
            y  = fmaf((W).y, r1[h].y, b1[h].y);                           \
            sa = fmaf(y, 0.65f, sa);                                      \
            sb = fmaf(k35.y, fabsf(y), sb);                               \
            y  = fmaf((W).z, r1[h].z, b1[h].z);                           \
            sa = fmaf(y, 0.65f, sa);                                      \
            sb = fmaf(k35.z, fabsf(y), sb);                               \
            y  = fmaf((W).w, r1[h].w, b1[h].w);                           \
            sa = fmaf(y, 0.65f, sa);                                      \
            sb = fmaf(k35.w, fabsf(y), sb);                               \
            (A)[h] = sa + sb;                                             \
        }                                                                 \
    }

__global__ __launch_bounds__(NTHR, 8)
void tse_kernel(const float* __restrict__ x,
                const float* __restrict__ w_att,
                const float* __restrict__ b_att,
                float* __restrict__ out)
{
    __shared__ __align__(16) float se[40 * NH];             // exp(scores) [n][h]
    __shared__ float sz[NWARP * NH];                        // per-warp Z partials
    __shared__ __align__(16) float4 sp4[NWARP * NH * NQ];   // partials (6.4 KB)

    const int tid  = threadIdx.x;
    const int warp = tid >> 5;
    const int lane = tid & 31;
    const int bid  = blockIdx.x;
    const float* __restrict__ xb = x + bid * (40 * DIM);
    const bool act = (lane < NQ);

    // ---- register params: r1 = t*wa, b1 = t*ba, k35 = copysign(0.35, t) ----
    float4 r1[NH], b1[NH], k35;
    #pragma unroll
    for (int h = 0; h < NH; h++) {
        r1[h] = make_float4(0.f, 0.f, 0.f, 0.f);
        b1[h] = make_float4(0.f, 0.f, 0.f, 0.f);
    }
    k35 = make_float4(0.f, 0.f, 0.f, 0.f);
    if (act) {
        const float4 t4 = reinterpret_cast<const float4*>(xb)[lane];
        k35.x = sgn035(t4.x); k35.y = sgn035(t4.y);
        k35.z = sgn035(t4.z); k35.w = sgn035(t4.w);
        #pragma unroll
        for (int h = 0; h < NH; h++) {
            const float4 wv = *reinterpret_cast<const float4*>(w_att + h * DIM + 4 * lane);
            const float4 bv = *reinterpret_cast<const float4*>(b_att + h * DIM + 4 * lane);
            r1[h].x = t4.x * wv.x; r1[h].y = t4.y * wv.y;
            r1[h].z = t4.z * wv.z; r1[h].w = t4.w * wv.w;
            b1[h].x = t4.x * bv.x; b1[h].y = t4.y * bv.y;
            b1[h].z = t4.z * bv.z; b1[h].w = t4.w * bv.w;
        }
    }

    const float* __restrict__ rp = xb + DIM + 4 * lane;
    const bool lo = (lane < 16);
    const bool b3 = (lane & 8)  != 0;
    const bool b2 = (lane & 4)  != 0;

    // ---- phase 1: dual-row iterations, merged 9-shuffle reduction ----
    float zacc = 0.f;
    #pragma unroll
    for (int k = 0; k < NIT; k++) {
        const int n0 = 2 * warp + 8 * k;     // always < NW
        const int n1 = n0 + 1;               // == NW only for warp 3, k = 4
        float4 wA = make_float4(0.f, 0.f, 0.f, 0.f);
        float4 wB = make_float4(0.f, 0.f, 0.f, 0.f);
        if (act) {
            wA = *reinterpret_cast<const float4*>(rp + n0 * DIM);
            if (n1 < NW)
                wB = *reinterpret_cast<const float4*>(rp + n1 * DIM);
        }

        // row A: scores + fold heads {2,3} into {0,1} at xor16
        float a[NH];
        SCORE4(a, wA);
        float xv  = __shfl_xor_sync(0xffffffffu, lo ? a[2] : a[0], 16);
        float yv  = __shfl_xor_sync(0xffffffffu, lo ? a[3] : a[1], 16);
        float uA0 = (lo ? a[0] : a[2]) + xv;
        float uA1 = (lo ? a[1] : a[3]) + yv;

        // row B: scores + fold at xor16 (overlaps row A's shuffle latency)
        SCORE4(a, wB);
        xv = __shfl_xor_sync(0xffffffffu, lo ? a[2] : a[0], 16);
        yv = __shfl_xor_sync(0xffffffffu, lo ? a[3] : a[1], 16);
        float uB0 = (lo ? a[0] : a[2]) + xv;
        float uB1 = (lo ? a[1] : a[3]) + yv;

        // fold remaining head bit at xor8 (per row)
        float tA = (b3 ? uA1 : uA0) + __shfl_xor_sync(0xffffffffu, b3 ? uA0 : uA1, 8);
        float tB = (b3 ? uB1 : uB0) + __shfl_xor_sync(0xffffffffu, b3 ? uB0 : uB1, 8);

        // merge rows at xor4: lane now owns (head = lane>>3, row = b2)
        float s = (b2 ? tB : tA) + __shfl_xor_sync(0xffffffffu, b2 ? tA : tB, 4);
        s += __shfl_xor_sync(0xffffffffu, s, 2);
        s += __shfl_xor_sync(0xffffffffu, s, 1);

        const float e = __expf(s);           // ONE exp covers all 8 (head,row) pairs
        const int nm = n0 + (b2 ? 1 : 0);
        if (nm < NW) {
            zacc += e;
            if ((lane & 3) == 0) se[nm * NH + (lane >> 3)] = e;
        }
    }
    // complete per-head Z across the two row-parities
    zacc += __shfl_xor_sync(0xffffffffu, zacc, 4);
    if ((lane & 7) == 0) sz[warp * NH + (lane >> 3)] = zacc;
    __syncwarp();   // phase 3 reads only this warp's se rows

    // ---- phase 3: dual-row accumulate (rows L1/L2-hot) ----
    float4 acc[NH];
    #pragma unroll
    for (int h = 0; h < NH; h++) acc[h] = make_float4(0.f, 0.f, 0.f, 0.f);

    #pragma unroll
    for (int k = 0; k < NIT; k++) {
        const int n0 = 2 * warp + 8 * k;
        const int n1 = n0 + 1;
        float4 wA = make_float4(0.f, 0.f, 0.f, 0.f);
        float4 wB = make_float4(0.f, 0.f, 0.f, 0.f);
        if (act) {
            wA = *reinterpret_cast<const float4*>(rp + n0 * DIM);
            if (n1 < NW)
                wB = *reinterpret_cast<const float4*>(rp + n1 * DIM);
        }
        const float4 eA = *reinterpret_cast<const float4*>(se + n0 * NH);
        float4 eB = make_float4(0.f, 0.f, 0.f, 0.f);
        if (n1 < NW) eB = *reinterpret_cast<const float4*>(se + n1 * NH);

        acc[0].x = fmaf(eA.x, wA.x, acc[0].x); acc[0].y = fmaf(eA.x, wA.y, acc[0].y);
        acc[0].z = fmaf(eA.x, wA.z, acc[0].z); acc[0].w = fmaf(eA.x, wA.w, acc[0].w);
        acc[1].x = fmaf(eA.y, wA.x, acc[1].x); acc[1].y = fmaf(eA.y, wA.y, acc[1].y);
        acc[1].z = fmaf(eA.y, wA.z, acc[1].z); acc[1].w = fmaf(eA.y, wA.w, acc[1].w);
        acc[2].x = fmaf(eA.z, wA.x, acc[2].x); acc[2].y = fmaf(eA.z, wA.y, acc[2].y);
        acc[2].z = fmaf(eA.z, wA.z, acc[2].z); acc[2].w = fmaf(eA.z, wA.w, acc[2].w);
        acc[3].x = fmaf(eA.w, wA.x, acc[3].x); acc[3].y = fmaf(eA.w, wA.y, acc[3].y);
        acc[3].z = fmaf(eA.w, wA.z, acc[3].z); acc[3].w = fmaf(eA.w, wA.w, acc[3].w);

        acc[0].x = fmaf(eB.x, wB.x, acc[0].x); acc[0].y = fmaf(eB.x, wB.y, acc[0].y);
        acc[0].z = fmaf(eB.x, wB.z, acc[0].z); acc[0].w = fmaf(eB.x, wB.w, acc[0].w);
        acc[1].x = fmaf(eB.y, wB.x, acc[1].x); acc[1].y = fmaf(eB.y, wB.y, acc[1].y);
        acc[1].z = fmaf(eB.y, wB.z, acc[1].z); acc[1].w = fmaf(eB.y, wB.w, acc[1].w);
        acc[2].x = fmaf(eB.z, wB.x, acc[2].x); acc[2].y = fmaf(eB.z, wB.y, acc[2].y);
        acc[2].z = fmaf(eB.z, wB.z, acc[2].z); acc[2].w = fmaf(eB.z, wB.w, acc[2].w);
        acc[3].x = fmaf(eB.w, wB.x, acc[3].x); acc[3].y = fmaf(eB.w, wB.y, acc[3].y);
        acc[3].z = fmaf(eB.w, wB.z, acc[3].z); acc[3].w = fmaf(eB.w, wB.w, acc[3].w);
    }

    // ---- per-warp partials + Z partials ----
    if (act) {
        #pragma unroll
        for (int h = 0; h < NH; h++)
            sp4[(warp * NH + h) * NQ + lane] = acc[h];
    }
    __syncthreads();   // single 128-thread barrier

    // ---- cross-warp reduce (4 partials) + normalize + float4 store ----
    if (tid < NH * NQ) {
        const int h = tid / NQ;
        const int i = tid - h * NQ;
        float4 v = sp4[h * NQ + i];
        float  Z = sz[h];
        #pragma unroll
        for (int w = 1; w < NWARP; w++) {
            const float4 p = sp4[(w * NH + h) * NQ + i];
            v.x += p.x; v.y += p.y; v.z += p.z; v.w += p.w;
            Z += sz[w * NH + h];
        }
        const float si = 1.f / Z;
        v.x *= si; v.y *= si; v.z *= si; v.w *= si;
        reinterpret_cast<float4*>(out + bid * (NH * DIM))[tid] = v;
    }
}

extern "C" void kernel_launch(void* const* d_in, const int* in_sizes, int n_in,
                              void* d_out, int out_size)
{
    const float* x     = (const float*)d_in[0];
    const float* w_att = (const float*)d_in[1];
    const float* b_att = (const float*)d_in[2];
    float* out = (float*)d_out;
    tse_kernel<<<NBLK, NTHR>>>(x, w_att, b_att, out);
}